// round 6
// baseline (speedup 1.0000x reference)
#include <cuda_runtime.h>

#define BATCH 1024
#define D_IN 3072
#define R_HID 128
#define NEXP 8
#define E_HID 2048
#define N_CLS 10

// Routing buckets (device globals — no allocation)
__device__ int   g_cnt[NEXP];
__device__ int   g_lb[NEXP][BATCH];
__device__ float g_lw[NEXP][BATCH];

__global__ void k_init() {
    if (threadIdx.x < NEXP) g_cnt[threadIdx.x] = 0;
}

// Router: 128 blocks x 128 threads, 8 samples/block.
// Also writes the routing-weighted eb2 bias directly into out.
__global__ void k_router(const float* __restrict__ x,
                         const float* __restrict__ rW1, const float* __restrict__ rb1,
                         const float* __restrict__ rW2, const float* __restrict__ rb2,
                         const float* __restrict__ eb2, float* __restrict__ out) {
    __shared__ float sX[8][512];
    __shared__ float sRh[8][R_HID];
    __shared__ float sLog[8][NEXP];
    const int tid = threadIdx.x;
    const int b0 = blockIdx.x * 8;

    float acc[8];
#pragma unroll
    for (int s = 0; s < 8; s++) acc[s] = 0.f;

    for (int kt = 0; kt < D_IN / 512; kt++) {
        __syncthreads();
        for (int i = tid; i < 8 * 512; i += 128) {
            int s = i >> 9, d = i & 511;
            sX[s][d] = x[(size_t)(b0 + s) * D_IN + kt * 512 + d];
        }
        __syncthreads();
#pragma unroll 4
        for (int d = 0; d < 512; d++) {
            float w = rW1[(size_t)(kt * 512 + d) * R_HID + tid];
#pragma unroll
            for (int s = 0; s < 8; s++) acc[s] = fmaf(sX[s][d], w, acc[s]);
        }
    }
    __syncthreads();
    float bias = rb1[tid];
#pragma unroll
    for (int s = 0; s < 8; s++) sRh[s][tid] = fmaxf(acc[s] + bias, 0.f);
    __syncthreads();

    if (tid < 64) {
        int s = tid >> 3, e = tid & 7;
        float l = rb2[e];
#pragma unroll 8
        for (int j = 0; j < R_HID; j++) l = fmaf(sRh[s][j], rW2[j * NEXP + e], l);
        sLog[s][e] = l;
    }
    __syncthreads();

    if (tid < 8) {
        int s = tid;
        int e0 = 0; float l0 = sLog[s][0];
        for (int e = 1; e < NEXP; e++) { float v = sLog[s][e]; if (v > l0) { l0 = v; e0 = e; } }
        int e1 = (e0 == 0) ? 1 : 0; float l1 = sLog[s][e1];
        for (int e = 0; e < NEXP; e++) {
            if (e == e0) continue;
            float v = sLog[s][e]; if (v > l1) { l1 = v; e1 = e; }
        }
        float w0 = 1.f / (1.f + expf(l1 - l0));
        float w1 = 1.f - w0;
        int b = b0 + s;
#pragma unroll
        for (int c = 0; c < N_CLS; c++)
            out[(size_t)b * N_CLS + c] = w0 * eb2[e0 * N_CLS + c] + w1 * eb2[e1 * N_CLS + c];
        int p0 = atomicAdd(&g_cnt[e0], 1); g_lb[e0][p0] = b; g_lw[e0][p0] = w0;
        int p1 = atomicAdd(&g_cnt[e1], 1); g_lb[e1][p1] = b; g_lw[e1][p1] = w1;
    }
}

__device__ __forceinline__ unsigned f2tf(float f) {
    unsigned u; asm("cvt.rna.tf32.f32 %0, %1;" : "=r"(u) : "f"(f)); return u;
}

#define MMA_TF32(acc, af, bf)                                                   \
    asm volatile("mma.sync.aligned.m16n8k8.row.col.f32.tf32.tf32.f32 "          \
                 "{%0,%1,%2,%3},{%4,%5,%6,%7},{%8,%9},{%0,%1,%2,%3};"           \
                 : "+f"(acc[0]), "+f"(acc[1]), "+f"(acc[2]), "+f"(acc[3])       \
                 : "r"(af[0]), "r"(af[1]), "r"(af[2]), "r"(af[3]),              \
                   "r"(bf[0]), "r"(bf[1]));

// A tile: [128][36] stride (bank = 4*quad+qt perm), B tile: [32][72] (bank = 8*qt+quad perm)
#define A_WORDS (128 * 36)
#define B_WORDS (32 * 72)
#define SMEM_BYTES ((2 * A_WORDS + 2 * B_WORDS) * 4)

// Expert GEMM (tf32 tensor cores) + fused relu + second GEMM.
// grid: (8 M-tiles, 8 experts, 32 h-tiles), 256 threads = 8 warps (4M x 2N).
// Block tile: 128 tokens x 64 h, warp tile 32x32, K staged 32, double-buffered.
__global__ void __launch_bounds__(256) k_expert(
    const float* __restrict__ x,
    const float* __restrict__ eW1, const float* __restrict__ eb1,
    const float* __restrict__ eW2, float* __restrict__ out)
{
    const int e = blockIdx.y;
    const int z = blockIdx.z;            // h tile: [z*64, z*64+64)
    const int n = g_cnt[e];
    const int start = blockIdx.x * 128;
    if (start >= n) return;

    extern __shared__ unsigned dsm[];
    unsigned* Abuf[2] = { dsm, dsm + A_WORDS };
    unsigned* Bbuf[2] = { dsm + 2 * A_WORDS, dsm + 2 * A_WORDS + B_WORDS };
    float (*eh)[68] = (float(*)[68])dsm;     // epilogue alias (34.8KB < 55.3KB)

    __shared__ int   sTok[128];
    __shared__ float sWt[128];

    const int tid  = threadIdx.x;
    const int lane = tid & 31, wid = tid >> 5;
    const int quad = lane >> 2, qt = lane & 3;
    const int warpM = wid & 3, warpN = wid >> 2;

    if (tid < 128) {
        int i = start + tid;
        if (i < n) { sTok[tid] = g_lb[e][i]; sWt[tid] = g_lw[e][i]; }
        else       { sTok[tid] = g_lb[e][start]; sWt[tid] = 0.f; }
    }
    __syncthreads();

    // Staging: 4 float4 of A + 2 float4 of B per thread per K=32 stage
    const int m0 = tid >> 3, kA = (tid & 7) * 4;
    const int r0 = tid >> 4, cB = (tid & 15) * 4;
    size_t tb[4];
#pragma unroll
    for (int i = 0; i < 4; i++) tb[i] = (size_t)sTok[m0 + 32 * i] * D_IN;
    const float* w1p = eW1 + (size_t)e * D_IN * E_HID + (size_t)z * 64;

    float4 av[4], bv[2];
#pragma unroll
    for (int i = 0; i < 4; i++) av[i] = *(const float4*)&x[tb[i] + kA];
#pragma unroll
    for (int i = 0; i < 2; i++) bv[i] = *(const float4*)&w1p[(size_t)(r0 + 16 * i) * E_HID + cB];

    float acc[2][4][4];
#pragma unroll
    for (int mt = 0; mt < 2; mt++)
#pragma unroll
        for (int nt = 0; nt < 4; nt++)
#pragma unroll
            for (int i = 0; i < 4; i++) acc[mt][nt][i] = 0.f;

    int buf = 0;
#pragma unroll 1
    for (int s = 0; s < D_IN / 32; s++) {
        {
            unsigned* A  = Abuf[buf];
            unsigned* Bm = Bbuf[buf];
            uint4 t;
#pragma unroll
            for (int i = 0; i < 4; i++) {
                t.x = f2tf(av[i].x); t.y = f2tf(av[i].y); t.z = f2tf(av[i].z); t.w = f2tf(av[i].w);
                *(uint4*)&A[(m0 + 32 * i) * 36 + kA] = t;
            }
#pragma unroll
            for (int i = 0; i < 2; i++) {
                t.x = f2tf(bv[i].x); t.y = f2tf(bv[i].y); t.z = f2tf(bv[i].z); t.w = f2tf(bv[i].w);
                *(uint4*)&Bm[(r0 + 16 * i) * 72 + cB] = t;
            }
        }
        __syncthreads();

        if (s + 1 < D_IN / 32) {
            int kg = (s + 1) * 32;
#pragma unroll
            for (int i = 0; i < 4; i++) av[i] = *(const float4*)&x[tb[i] + kg + kA];
#pragma unroll
            for (int i = 0; i < 2; i++)
                bv[i] = *(const float4*)&w1p[(size_t)(kg + r0 + 16 * i) * E_HID + cB];
        }

        const unsigned* A  = Abuf[buf];
        const unsigned* Bm = Bbuf[buf];
#pragma unroll
        for (int ks = 0; ks < 4; ks++) {
            const int kq = ks * 8 + qt;
            unsigned af[2][4], bf[4][2];
#pragma unroll
            for (int mt = 0; mt < 2; mt++) {
                int r = warpM * 32 + mt * 16 + quad;
                af[mt][0] = A[r * 36 + kq];
                af[mt][1] = A[(r + 8) * 36 + kq];
                af[mt][2] = A[r * 36 + kq + 4];
                af[mt][3] = A[(r + 8) * 36 + kq + 4];
            }
#pragma unroll
            for (int nt = 0; nt < 4; nt++) {
                int c = warpN * 32 + nt * 8 + quad;
                bf[nt][0] = Bm[kq * 72 + c];
                bf[nt][1] = Bm[(kq + 4) * 72 + c];
            }
#pragma unroll
            for (int mt = 0; mt < 2; mt++)
#pragma unroll
                for (int nt = 0; nt < 4; nt++)
                    MMA_TF32(acc[mt][nt], af[mt], bf[nt]);
        }
        buf ^= 1;
        __syncthreads();   // protect buf we are about to overwrite (double buffer wrap)
    }

    // Epilogue: bias + relu into smem eh tile (aliases A/B buffers)
    const float* b1p = eb1 + (size_t)e * E_HID + (size_t)z * 64;
#pragma unroll
    for (int mt = 0; mt < 2; mt++) {
#pragma unroll
        for (int nt = 0; nt < 4; nt++) {
            int r = warpM * 32 + mt * 16 + quad;
            int c = warpN * 32 + nt * 8 + qt * 2;
            float vb0 = b1p[c], vb1 = b1p[c + 1];
            eh[r][c]         = fmaxf(acc[mt][nt][0] + vb0, 0.f);
            eh[r][c + 1]     = fmaxf(acc[mt][nt][1] + vb1, 0.f);
            eh[r + 8][c]     = fmaxf(acc[mt][nt][2] + vb0, 0.f);
            eh[r + 8][c + 1] = fmaxf(acc[mt][nt][3] + vb1, 0.f);
        }
    }
    __syncthreads();

    // Second GEMM: out[tok][c] += w_tok * sum_h eh[tok][h] * eW2[e][z*64+h][c]
    for (int idx = tid; idx < 128 * N_CLS; idx += 256) {
        int t = idx / N_CLS, c = idx % N_CLS;
        float wgt = sWt[t];
        if (wgt != 0.f) {
            const float* w2p = eW2 + ((size_t)e * E_HID + (size_t)z * 64) * N_CLS + c;
            float s0 = 0.f, s1 = 0.f, s2 = 0.f, s3 = 0.f;
#pragma unroll
            for (int h = 0; h < 64; h += 4) {
                s0 = fmaf(eh[t][h],     w2p[(h)     * N_CLS], s0);
                s1 = fmaf(eh[t][h + 1], w2p[(h + 1) * N_CLS], s1);
                s2 = fmaf(eh[t][h + 2], w2p[(h + 2) * N_CLS], s2);
                s3 = fmaf(eh[t][h + 3], w2p[(h + 3) * N_CLS], s3);
            }
            atomicAdd(&out[(size_t)sTok[t] * N_CLS + c], wgt * ((s0 + s1) + (s2 + s3)));
        }
    }
}

extern "C" void kernel_launch(void* const* d_in, const int* in_sizes, int n_in,
                              void* d_out, int out_size) {
    const float* x   = (const float*)d_in[0];
    const float* rW1 = (const float*)d_in[1];
    const float* rb1 = (const float*)d_in[2];
    const float* rW2 = (const float*)d_in[3];
    const float* rb2 = (const float*)d_in[4];
    const float* eW1 = (const float*)d_in[5];
    const float* eb1 = (const float*)d_in[6];
    const float* eW2 = (const float*)d_in[7];
    const float* eb2 = (const float*)d_in[8];
    float* out = (float*)d_out;

    cudaFuncSetAttribute(k_expert, cudaFuncAttributeMaxDynamicSharedMemorySize, SMEM_BYTES);

    k_init<<<1, 32>>>();
    k_router<<<BATCH / 8, 128>>>(x, rW1, rb1, rW2, rb2, eb2, out);
    dim3 g(BATCH / 128, NEXP, E_HID / 64);
    k_expert<<<g, 256, SMEM_BYTES>>>(x, eW1, eb1, eW2, out);
}

// round 7
// speedup vs baseline: 1.0045x; 1.0045x over previous
#include <cuda_runtime.h>

#define BATCH 1024
#define D_IN 3072
#define R_HID 128
#define NEXP 8
#define E_HID 2048
#define N_CLS 10

// Routing buckets (device globals — no allocation)
__device__ int   g_cnt[NEXP];
__device__ int   g_lb[NEXP][BATCH];
__device__ float g_lw[NEXP][BATCH];

__global__ void k_init() {
    if (threadIdx.x < NEXP) g_cnt[threadIdx.x] = 0;
}

// Router: 128 blocks x 128 threads, 8 samples/block.
// Also writes the routing-weighted eb2 bias directly into out.
__global__ void k_router(const float* __restrict__ x,
                         const float* __restrict__ rW1, const float* __restrict__ rb1,
                         const float* __restrict__ rW2, const float* __restrict__ rb2,
                         const float* __restrict__ eb2, float* __restrict__ out) {
    __shared__ float sX[8][512];
    __shared__ float sRh[8][R_HID];
    __shared__ float sLog[8][NEXP];
    const int tid = threadIdx.x;
    const int b0 = blockIdx.x * 8;

    float acc[8];
#pragma unroll
    for (int s = 0; s < 8; s++) acc[s] = 0.f;

    for (int kt = 0; kt < D_IN / 512; kt++) {
        __syncthreads();
        for (int i = tid; i < 8 * 512; i += 128) {
            int s = i >> 9, d = i & 511;
            sX[s][d] = x[(size_t)(b0 + s) * D_IN + kt * 512 + d];
        }
        __syncthreads();
#pragma unroll 4
        for (int d = 0; d < 512; d++) {
            float w = rW1[(size_t)(kt * 512 + d) * R_HID + tid];
#pragma unroll
            for (int s = 0; s < 8; s++) acc[s] = fmaf(sX[s][d], w, acc[s]);
        }
    }
    __syncthreads();
    float bias = rb1[tid];
#pragma unroll
    for (int s = 0; s < 8; s++) sRh[s][tid] = fmaxf(acc[s] + bias, 0.f);
    __syncthreads();

    if (tid < 64) {
        int s = tid >> 3, e = tid & 7;
        float l = rb2[e];
#pragma unroll 8
        for (int j = 0; j < R_HID; j++) l = fmaf(sRh[s][j], rW2[j * NEXP + e], l);
        sLog[s][e] = l;
    }
    __syncthreads();

    if (tid < 8) {
        int s = tid;
        int e0 = 0; float l0 = sLog[s][0];
        for (int e = 1; e < NEXP; e++) { float v = sLog[s][e]; if (v > l0) { l0 = v; e0 = e; } }
        int e1 = (e0 == 0) ? 1 : 0; float l1 = sLog[s][e1];
        for (int e = 0; e < NEXP; e++) {
            if (e == e0) continue;
            float v = sLog[s][e]; if (v > l1) { l1 = v; e1 = e; }
        }
        float w0 = 1.f / (1.f + expf(l1 - l0));
        float w1 = 1.f - w0;
        int b = b0 + s;
#pragma unroll
        for (int c = 0; c < N_CLS; c++)
            out[(size_t)b * N_CLS + c] = w0 * eb2[e0 * N_CLS + c] + w1 * eb2[e1 * N_CLS + c];
        int p0 = atomicAdd(&g_cnt[e0], 1); g_lb[e0][p0] = b; g_lw[e0][p0] = w0;
        int p1 = atomicAdd(&g_cnt[e1], 1); g_lb[e1][p1] = b; g_lw[e1][p1] = w1;
    }
}

__device__ __forceinline__ unsigned f2tf(float f) {
    unsigned u; asm("cvt.rna.tf32.f32 %0, %1;" : "=r"(u) : "f"(f)); return u;
}

#define MMA_TF32(acc, af, bf)                                                   \
    asm volatile("mma.sync.aligned.m16n8k8.row.col.f32.tf32.tf32.f32 "          \
                 "{%0,%1,%2,%3},{%4,%5,%6,%7},{%8,%9},{%0,%1,%2,%3};"           \
                 : "+f"(acc[0]), "+f"(acc[1]), "+f"(acc[2]), "+f"(acc[3])       \
                 : "r"(af[0]), "r"(af[1]), "r"(af[2]), "r"(af[3]),              \
                   "r"(bf[0]), "r"(bf[1]));

// A tile: [128][36] stride (bank = 4*quad+qt perm), B tile: [32][72] (bank = 8*qt+quad perm)
#define A_WORDS (128 * 36)
#define B_WORDS (32 * 72)
#define SMEM_BYTES ((2 * A_WORDS + 2 * B_WORDS) * 4)

// Expert GEMM (tf32 tensor cores) + fused relu + second GEMM.
// grid: (8 M-tiles, 8 experts, 32 h-tiles), 256 threads = 8 warps (4M x 2N).
// Block tile: 128 tokens x 64 h, warp tile 32x32, K staged 32, double-buffered.
__global__ void __launch_bounds__(256) k_expert(
    const float* __restrict__ x,
    const float* __restrict__ eW1, const float* __restrict__ eb1,
    const float* __restrict__ eW2, float* __restrict__ out)
{
    const int e = blockIdx.y;
    const int z = blockIdx.z;            // h tile: [z*64, z*64+64)
    const int n = g_cnt[e];
    const int start = blockIdx.x * 128;
    if (start >= n) return;

    extern __shared__ unsigned dsm[];
    unsigned* Abuf[2] = { dsm, dsm + A_WORDS };
    unsigned* Bbuf[2] = { dsm + 2 * A_WORDS, dsm + 2 * A_WORDS + B_WORDS };
    float (*eh)[68] = (float(*)[68])dsm;     // epilogue alias (34.8KB < 55.3KB)

    __shared__ int   sTok[128];
    __shared__ float sWt[128];

    const int tid  = threadIdx.x;
    const int lane = tid & 31, wid = tid >> 5;
    const int quad = lane >> 2, qt = lane & 3;
    const int warpM = wid & 3, warpN = wid >> 2;

    if (tid < 128) {
        int i = start + tid;
        if (i < n) { sTok[tid] = g_lb[e][i]; sWt[tid] = g_lw[e][i]; }
        else       { sTok[tid] = g_lb[e][start]; sWt[tid] = 0.f; }
    }
    __syncthreads();

    // Staging: 4 float4 of A + 2 float4 of B per thread per K=32 stage
    const int m0 = tid >> 3, kA = (tid & 7) * 4;
    const int r0 = tid >> 4, cB = (tid & 15) * 4;
    size_t tb[4];
#pragma unroll
    for (int i = 0; i < 4; i++) tb[i] = (size_t)sTok[m0 + 32 * i] * D_IN;
    const float* w1p = eW1 + (size_t)e * D_IN * E_HID + (size_t)z * 64;

    float4 av[4], bv[2];
#pragma unroll
    for (int i = 0; i < 4; i++) av[i] = *(const float4*)&x[tb[i] + kA];
#pragma unroll
    for (int i = 0; i < 2; i++) bv[i] = *(const float4*)&w1p[(size_t)(r0 + 16 * i) * E_HID + cB];

    float acc[2][4][4];
#pragma unroll
    for (int mt = 0; mt < 2; mt++)
#pragma unroll
        for (int nt = 0; nt < 4; nt++)
#pragma unroll
            for (int i = 0; i < 4; i++) acc[mt][nt][i] = 0.f;

    int buf = 0;
#pragma unroll 1
    for (int s = 0; s < D_IN / 32; s++) {
        {
            unsigned* A  = Abuf[buf];
            unsigned* Bm = Bbuf[buf];
            uint4 t;
#pragma unroll
            for (int i = 0; i < 4; i++) {
                t.x = f2tf(av[i].x); t.y = f2tf(av[i].y); t.z = f2tf(av[i].z); t.w = f2tf(av[i].w);
                *(uint4*)&A[(m0 + 32 * i) * 36 + kA] = t;
            }
#pragma unroll
            for (int i = 0; i < 2; i++) {
                t.x = f2tf(bv[i].x); t.y = f2tf(bv[i].y); t.z = f2tf(bv[i].z); t.w = f2tf(bv[i].w);
                *(uint4*)&Bm[(r0 + 16 * i) * 72 + cB] = t;
            }
        }
        __syncthreads();

        if (s + 1 < D_IN / 32) {
            int kg = (s + 1) * 32;
#pragma unroll
            for (int i = 0; i < 4; i++) av[i] = *(const float4*)&x[tb[i] + kg + kA];
#pragma unroll
            for (int i = 0; i < 2; i++)
                bv[i] = *(const float4*)&w1p[(size_t)(kg + r0 + 16 * i) * E_HID + cB];
        }

        const unsigned* A  = Abuf[buf];
        const unsigned* Bm = Bbuf[buf];
#pragma unroll
        for (int ks = 0; ks < 4; ks++) {
            const int kq = ks * 8 + qt;
            unsigned af[2][4], bf[4][2];
#pragma unroll
            for (int mt = 0; mt < 2; mt++) {
                int r = warpM * 32 + mt * 16 + quad;
                af[mt][0] = A[r * 36 + kq];
                af[mt][1] = A[(r + 8) * 36 + kq];
                af[mt][2] = A[r * 36 + kq + 4];
                af[mt][3] = A[(r + 8) * 36 + kq + 4];
            }
#pragma unroll
            for (int nt = 0; nt < 4; nt++) {
                int c = warpN * 32 + nt * 8 + quad;
                bf[nt][0] = Bm[kq * 72 + c];
                bf[nt][1] = Bm[(kq + 4) * 72 + c];
            }
#pragma unroll
            for (int mt = 0; mt < 2; mt++)
#pragma unroll
                for (int nt = 0; nt < 4; nt++)
                    MMA_TF32(acc[mt][nt], af[mt], bf[nt]);
        }
        buf ^= 1;
        __syncthreads();   // protect buf we are about to overwrite (double buffer wrap)
    }

    // Epilogue: bias + relu into smem eh tile (aliases A/B buffers)
    const float* b1p = eb1 + (size_t)e * E_HID + (size_t)z * 64;
#pragma unroll
    for (int mt = 0; mt < 2; mt++) {
#pragma unroll
        for (int nt = 0; nt < 4; nt++) {
            int r = warpM * 32 + mt * 16 + quad;
            int c = warpN * 32 + nt * 8 + qt * 2;
            float vb0 = b1p[c], vb1 = b1p[c + 1];
            eh[r][c]         = fmaxf(acc[mt][nt][0] + vb0, 0.f);
            eh[r][c + 1]     = fmaxf(acc[mt][nt][1] + vb1, 0.f);
            eh[r + 8][c]     = fmaxf(acc[mt][nt][2] + vb0, 0.f);
            eh[r + 8][c + 1] = fmaxf(acc[mt][nt][3] + vb1, 0.f);
        }
    }
    __syncthreads();

    // Second GEMM: out[tok][c] += w_tok * sum_h eh[tok][h] * eW2[e][z*64+h][c]
    for (int idx = tid; idx < 128 * N_CLS; idx += 256) {
        int t = idx / N_CLS, c = idx % N_CLS;
        float wgt = sWt[t];
        if (wgt != 0.f) {
            const float* w2p = eW2 + ((size_t)e * E_HID + (size_t)z * 64) * N_CLS + c;
            float s0 = 0.f, s1 = 0.f, s2 = 0.f, s3 = 0.f;
#pragma unroll
            for (int h = 0; h < 64; h += 4) {
                s0 = fmaf(eh[t][h],     w2p[(h)     * N_CLS], s0);
                s1 = fmaf(eh[t][h + 1], w2p[(h + 1) * N_CLS], s1);
                s2 = fmaf(eh[t][h + 2], w2p[(h + 2) * N_CLS], s2);
                s3 = fmaf(eh[t][h + 3], w2p[(h + 3) * N_CLS], s3);
            }
            atomicAdd(&out[(size_t)sTok[t] * N_CLS + c], wgt * ((s0 + s1) + (s2 + s3)));
        }
    }
}

extern "C" void kernel_launch(void* const* d_in, const int* in_sizes, int n_in,
                              void* d_out, int out_size) {
    const float* x   = (const float*)d_in[0];
    const float* rW1 = (const float*)d_in[1];
    const float* rb1 = (const float*)d_in[2];
    const float* rW2 = (const float*)d_in[3];
    const float* rb2 = (const float*)d_in[4];
    const float* eW1 = (const float*)d_in[5];
    const float* eb1 = (const float*)d_in[6];
    const float* eW2 = (const float*)d_in[7];
    const float* eb2 = (const float*)d_in[8];
    float* out = (float*)d_out;

    cudaFuncSetAttribute(k_expert, cudaFuncAttributeMaxDynamicSharedMemorySize, SMEM_BYTES);

    k_init<<<1, 32>>>();
    k_router<<<BATCH / 8, 128>>>(x, rW1, rb1, rW2, rb2, eb2, out);
    dim3 g(BATCH / 128, NEXP, E_HID / 64);
    k_expert<<<g, 256, SMEM_BYTES>>>(x, eW1, eb1, eW2, out);
}